// round 8
// baseline (speedup 1.0000x reference)
#include <cuda_runtime.h>
#include <cuda_bf16.h>
#include <cstdint>

#define N_NODES 50000
#define N_EDGES 800000
#define IN_DIM  128
#define HID     128
#define OUT_DIM 64
#define CAP     96          // max in-degree (Poisson λ=16 → P(>96) ~ 0)

typedef unsigned long long u64;

// Scratch (device globals — no allocations allowed)
__device__ int   g_idx64;                         // 1 if edge_index is int64
__device__ int   g_cur[N_NODES];                  // cursor == in-degree after fill
__device__ float g_dinv[N_NODES];
__device__ float g_hs[(size_t)N_NODES * IN_DIM];  // h[r] * dinv[r]
__device__ int   g_src[(size_t)N_NODES * CAP];    // bucketed source lists (19.2 MB)
__device__ u64   g_Wg2[IN_DIM * HID];             // Wg duplicated into both f32x2 lanes
__device__ u64   g_Wf2[HID * OUT_DIM];            // Wf duplicated

// ---- f32x2 helpers (FFMA2: scalar FFMA is half-rate rt=2 on sm_103a) ----
__device__ __forceinline__ u64 fma2(u64 a, u64 b, u64 c) {
    u64 d;
    asm("fma.rn.f32x2 %0, %1, %2, %3;" : "=l"(d) : "l"(a), "l"(b), "l"(c));
    return d;
}
__device__ __forceinline__ u64 pack2(float lo, float hi) {
    u64 r;
    asm("mov.b64 %0, {%1, %2};" : "=l"(r) : "f"(lo), "f"(hi));
    return r;
}
__device__ __forceinline__ float2 unpack2(u64 v) {
    float2 r;
    asm("mov.b64 {%0, %1}, %2;" : "=f"(r.x), "=f"(r.y) : "l"(v));
    return r;
}

__device__ __forceinline__ int edge_idx(const void* ei, int i) {
    if (g_idx64) return (int)((const long long*)ei)[i];
    return ((const int*)ei)[i];
}

// ---------------------------------------------------------------------------
// k0: zero cursors + duplicate weights into f32x2 lanes + dtype detection
// ---------------------------------------------------------------------------
__global__ void k_init(const void* __restrict__ ei,
                       const float* __restrict__ Wg,
                       const float* __restrict__ Wf) {
    int i = blockIdx.x * blockDim.x + threadIdx.x;
    if (i < N_NODES) g_cur[i] = 0;
    if (i < IN_DIM * HID) { float w = Wg[i]; g_Wg2[i] = pack2(w, w); }
    if (i < HID * OUT_DIM) { float w = Wf[i]; g_Wf2[i] = pack2(w, w); }
    if (blockIdx.x == 0) {
        __shared__ int s_ok;
        if (threadIdx.x == 0) s_ok = 1;
        __syncthreads();
        long long v = ((const long long*)ei)[threadIdx.x];  // 2KB, in-bounds either way
        if (v < 0 || v >= N_NODES) atomicAnd(&s_ok, 0);
        __syncthreads();
        if (threadIdx.x == 0) g_idx64 = s_ok;
    }
}

// k1: combined count + bucket fill (cursor doubles as in-degree histogram)
__global__ void k_fill(const void* __restrict__ ei) {
    int e = blockIdx.x * blockDim.x + threadIdx.x;
    if (e < N_EDGES) {
        int r = edge_idx(ei, e);
        int c = edge_idx(ei, N_EDGES + e);
        int p = atomicAdd(&g_cur[c], 1);
        if (p < CAP) g_src[(size_t)c * CAP + p] = r;
    }
}

// k2: dinv = rsqrt(deg+1), hs = h * dinv
__global__ void k_hs(const float* __restrict__ h) {
    int idx = blockIdx.x * blockDim.x + threadIdx.x;
    if (idx >= N_NODES * 32) return;
    int node = idx >> 5;
    float dn = rsqrtf((float)(g_cur[node] + 1));   // +1 self-loop
    if ((idx & 31) == 0) g_dinv[node] = dn;
    float4 v = ((const float4*)h)[idx];
    v.x *= dn; v.y *= dn; v.z *= dn; v.w *= dn;
    ((float4*)g_hs)[idx] = v;
}

// ---------------------------------------------------------------------------
// k3: fused gather + FFMA2 MLP.
//   Tile stored TRANSPOSED+swizzled in smem: addr(k,node) = k*64 + (node ^ sw(k)),
//   sw(k) = 2*((k>>2)&15). Loads (warp-uniform node) broadcast; stores <=2-way.
//   Phase accumulators pair NODES in f32x2 lanes -> same reg count as scalar,
//   half the FMA-pipe issues. Per-lane k-order identical to scalar (same numerics).
// ---------------------------------------------------------------------------
__global__ void __launch_bounds__(256) k_gather_mlp(const float* __restrict__ bg,
                                                    const float* __restrict__ bf,
                                                    float* __restrict__ out) {
    __shared__ float sA[128 * 64];   // 32 KB: transposed agg tile, then hidden tile

    int tid = threadIdx.x;
    int tx = tid & 31;       // lane
    int ty = tid >> 5;       // warp
    int node0 = blockIdx.x * 64;
    const float4* hs4 = (const float4*)g_hs;
    int swt = 2 * (tx & 15);          // store swizzle for this lane (k>>2 == tx)

    // ---- gather phase (x4 unrolled, proven) ----
    #pragma unroll
    for (int j = 0; j < 8; j++) {
        int nl = ty * 8 + j;          // local node
        int node = node0 + nl;
        float4 acc = make_float4(0.f, 0.f, 0.f, 0.f);
        if (node < N_NODES) {
            acc = __ldg(hs4 + (size_t)node * 32 + tx);          // self term
            int cnt = __ldg(g_cur + node);
            if (cnt > CAP) cnt = CAP;
            const int* src = g_src + (size_t)node * CAP;
            int p = 0;
            for (; p + 4 <= cnt; p += 4) {
                int r0 = __ldg(src + p + 0);
                int r1 = __ldg(src + p + 1);
                int r2 = __ldg(src + p + 2);
                int r3 = __ldg(src + p + 3);
                float4 v0 = __ldg(hs4 + (size_t)r0 * 32 + tx);
                float4 v1 = __ldg(hs4 + (size_t)r1 * 32 + tx);
                float4 v2 = __ldg(hs4 + (size_t)r2 * 32 + tx);
                float4 v3 = __ldg(hs4 + (size_t)r3 * 32 + tx);
                acc.x += v0.x + v1.x + v2.x + v3.x;
                acc.y += v0.y + v1.y + v2.y + v3.y;
                acc.z += v0.z + v1.z + v2.z + v3.z;
                acc.w += v0.w + v1.w + v2.w + v3.w;
            }
            for (; p < cnt; p++) {
                int r = __ldg(src + p);
                float4 v = __ldg(hs4 + (size_t)r * 32 + tx);
                acc.x += v.x; acc.y += v.y; acc.z += v.z; acc.w += v.w;
            }
            float dn = __ldg(g_dinv + node);
            acc.x *= dn; acc.y *= dn; acc.z *= dn; acc.w *= dn;
        }
        // transposed swizzled store: rows k = 4tx..4tx+3
        int colA = nl ^ swt;
        sA[(4 * tx + 0) * 64 + colA] = acc.x;
        sA[(4 * tx + 1) * 64 + colA] = acc.y;
        sA[(4 * tx + 2) * 64 + colA] = acc.z;
        sA[(4 * tx + 3) * 64 + colA] = acc.w;
    }
    __syncthreads();

    // ---- phase 1: hid = A @ Wg + bg  (4 node-pairs x 4 cols, f32x2 over nodes) ----
    u64 acc2[4][4];
    {
        float4 b = __ldg((const float4*)bg + tx);
        #pragma unroll
        for (int i = 0; i < 4; i++) {
            acc2[i][0] = pack2(b.x, b.x);
            acc2[i][1] = pack2(b.y, b.y);
            acc2[i][2] = pack2(b.z, b.z);
            acc2[i][3] = pack2(b.w, b.w);
        }
    }
    #pragma unroll 4
    for (int k = 0; k < 128; k++) {
        const u64* wrow = g_Wg2 + k * 128 + 4 * tx;
        longlong2 wa = __ldg((const longlong2*)wrow);       // cols 4tx, 4tx+1
        longlong2 wb = __ldg((const longlong2*)(wrow + 2)); // cols 4tx+2, 4tx+3
        int sw = 2 * ((k >> 2) & 15);
        const float* row = sA + k * 64;
        #pragma unroll
        for (int i = 0; i < 4; i++) {
            u64 a2 = *(const u64*)&row[(8 * ty + 2 * i) ^ sw];  // node pair, bcast
            acc2[i][0] = fma2(a2, (u64)wa.x, acc2[i][0]);
            acc2[i][1] = fma2(a2, (u64)wa.y, acc2[i][1]);
            acc2[i][2] = fma2(a2, (u64)wb.x, acc2[i][2]);
            acc2[i][3] = fma2(a2, (u64)wb.y, acc2[i][3]);
        }
    }
    __syncthreads();

    // relu -> hidden tile, transposed swizzled (row = hid col c, c>>2 == tx)
    #pragma unroll
    for (int i = 0; i < 4; i++) {
        int nl = 8 * ty + 2 * i;
        int colH = nl ^ swt;
        #pragma unroll
        for (int j = 0; j < 4; j++) {
            float2 v = unpack2(acc2[i][j]);
            v.x = fmaxf(v.x, 0.f);
            v.y = fmaxf(v.y, 0.f);
            *(u64*)&sA[(4 * tx + j) * 64 + colH] = pack2(v.x, v.y);
        }
    }
    __syncthreads();

    // ---- phase 2: out = hid @ Wf + bf  (4 node-pairs x 2 cols) ----
    u64 o2[4][2];
    {
        float2 b = __ldg((const float2*)bf + tx);
        #pragma unroll
        for (int i = 0; i < 4; i++) {
            o2[i][0] = pack2(b.x, b.x);
            o2[i][1] = pack2(b.y, b.y);
        }
    }
    #pragma unroll 4
    for (int k = 0; k < 128; k++) {
        longlong2 w = __ldg((const longlong2*)(g_Wf2 + k * 64 + 2 * tx));
        int sw = 2 * ((k >> 2) & 15);
        const float* row = sA + k * 64;
        #pragma unroll
        for (int i = 0; i < 4; i++) {
            u64 a2 = *(const u64*)&row[(8 * ty + 2 * i) ^ sw];
            o2[i][0] = fma2(a2, (u64)w.x, o2[i][0]);
            o2[i][1] = fma2(a2, (u64)w.y, o2[i][1]);
        }
    }

    #pragma unroll
    for (int i = 0; i < 4; i++) {
        int ne = node0 + 8 * ty + 2 * i;      // even node of pair
        float2 c0 = unpack2(o2[i][0]);        // col 2tx   : (node_e, node_o)
        float2 c1 = unpack2(o2[i][1]);        // col 2tx+1 : (node_e, node_o)
        if (ne < N_NODES) {
            float2 v; v.x = c0.x; v.y = c1.x;
            ((float2*)out)[(size_t)ne * 32 + tx] = v;
        }
        if (ne + 1 < N_NODES) {
            float2 v; v.x = c0.y; v.y = c1.y;
            ((float2*)out)[(size_t)(ne + 1) * 32 + tx] = v;
        }
    }
}

// ---------------------------------------------------------------------------
// launch — inputs: h[f32 N*128], edge_index[2*E int32-or-int64],
//          W_gcn[f32 128*128], b_gcn[f32 128], W_fc[f32 128*64], b_fc[f32 64]
// output: f32 N*64
// ---------------------------------------------------------------------------
extern "C" void kernel_launch(void* const* d_in, const int* in_sizes, int n_in,
                              void* d_out, int out_size) {
    const float* h  = (const float*)d_in[0];
    const void*  ei = d_in[1];
    const float* Wg = (const float*)d_in[2];
    const float* bg = (const float*)d_in[3];
    const float* Wf = (const float*)d_in[4];
    const float* bf = (const float*)d_in[5];
    float* out = (float*)d_out;

    k_init<<<(N_NODES + 255) / 256, 256>>>(ei, Wg, Wf);
    k_fill<<<(N_EDGES + 255) / 256, 256>>>(ei);
    k_hs  <<<(N_NODES * 32 + 255) / 256, 256>>>(h);
    k_gather_mlp<<<(N_NODES + 63) / 64, 256>>>(bg, bf, out);
}

// round 9
// speedup vs baseline: 1.0258x; 1.0258x over previous
#include <cuda_runtime.h>
#include <cuda_bf16.h>
#include <cstdint>

#define N_NODES 50000
#define N_EDGES 800000
#define IN_DIM  128
#define HID     128
#define OUT_DIM 64
#define CAP     96          // max in-degree (Poisson λ=16 → P(>96) ~ 0)

// Scratch (device globals — no allocations allowed)
__device__ int   g_idx64;                         // 1 if edge_index is int64
__device__ int   g_cur[N_NODES];                  // cursor == in-degree after fill
__device__ float g_dinv[N_NODES];
__device__ float g_hs[(size_t)N_NODES * IN_DIM];  // h[r] * dinv[r]
__device__ int   g_src[(size_t)N_NODES * CAP];    // bucketed source lists (19.2 MB)

__device__ __forceinline__ int edge_idx(const void* ei, int i) {
    if (g_idx64) return (int)((const long long*)ei)[i];
    return ((const int*)ei)[i];
}

// ---------------------------------------------------------------------------
// k0: zero cursors + dtype detection (JAX silently downcasts int64 -> int32)
// ---------------------------------------------------------------------------
__global__ void k_init(const void* __restrict__ ei) {
    int i = blockIdx.x * blockDim.x + threadIdx.x;
    if (i < N_NODES) g_cur[i] = 0;
    if (blockIdx.x == 0) {
        __shared__ int s_ok;
        if (threadIdx.x == 0) s_ok = 1;
        __syncthreads();
        long long v = ((const long long*)ei)[threadIdx.x];  // 2KB, in-bounds either way
        if (v < 0 || v >= N_NODES) atomicAnd(&s_ok, 0);
        __syncthreads();
        if (threadIdx.x == 0) g_idx64 = s_ok;
    }
}

// k1: combined count + bucket fill (cursor doubles as in-degree histogram)
__global__ void k_fill(const void* __restrict__ ei) {
    int e = blockIdx.x * blockDim.x + threadIdx.x;
    if (e < N_EDGES) {
        int r = edge_idx(ei, e);
        int c = edge_idx(ei, N_EDGES + e);
        int p = atomicAdd(&g_cur[c], 1);
        if (p < CAP) g_src[(size_t)c * CAP + p] = r;
    }
}

// k2: dinv = rsqrt(deg+1), hs = h * dinv
__global__ void k_hs(const float* __restrict__ h) {
    int idx = blockIdx.x * blockDim.x + threadIdx.x;
    if (idx >= N_NODES * 32) return;
    int node = idx >> 5;
    float dn = rsqrtf((float)(g_cur[node] + 1));   // +1 self-loop
    if ((idx & 31) == 0) g_dinv[node] = dn;
    float4 v = ((const float4*)h)[idx];
    v.x *= dn; v.y *= dn; v.z *= dn; v.w *= dn;
    ((float4*)g_hs)[idx] = v;
}

// ---------------------------------------------------------------------------
// k3: fused gather + MLP (proven R7 structure; launch_bounds(256,4) to get
//     4 CTAs/SM instead of 3 — more warps to hide gather L2 latency).
//   256 threads = 8 warps; 64 nodes per block; warp ty owns nodes 8ty..8ty+7.
//   Gather: agg[n] = dinv[n]*(hs[n] + sum_in hs[r]); edge loop unrolled x4.
//   MLP: out = relu(tile @ Wg + bg) @ Wf + bf  (scalar register tile).
// ---------------------------------------------------------------------------
__global__ void __launch_bounds__(256, 4) k_gather_mlp(const float* __restrict__ Wg,
                                                       const float* __restrict__ bg,
                                                       const float* __restrict__ Wf,
                                                       const float* __restrict__ bf,
                                                       float* __restrict__ out) {
    __shared__ float sA[64 * 128];   // 32 KB: aggregated tile, then hidden tile

    int tid = threadIdx.x;
    int tx = tid & 31;       // lane
    int ty = tid >> 5;       // warp
    int node0 = blockIdx.x * 64;
    const float4* hs4 = (const float4*)g_hs;

    // ---- gather phase ----
    #pragma unroll
    for (int j = 0; j < 8; j++) {
        int node = node0 + ty * 8 + j;
        float4 acc = make_float4(0.f, 0.f, 0.f, 0.f);
        if (node < N_NODES) {
            acc = __ldg(hs4 + (size_t)node * 32 + tx);          // self term
            int cnt = __ldg(g_cur + node);
            if (cnt > CAP) cnt = CAP;
            const int* src = g_src + (size_t)node * CAP;
            int p = 0;
            for (; p + 4 <= cnt; p += 4) {
                int r0 = __ldg(src + p + 0);
                int r1 = __ldg(src + p + 1);
                int r2 = __ldg(src + p + 2);
                int r3 = __ldg(src + p + 3);
                float4 v0 = __ldg(hs4 + (size_t)r0 * 32 + tx);
                float4 v1 = __ldg(hs4 + (size_t)r1 * 32 + tx);
                float4 v2 = __ldg(hs4 + (size_t)r2 * 32 + tx);
                float4 v3 = __ldg(hs4 + (size_t)r3 * 32 + tx);
                acc.x += v0.x + v1.x + v2.x + v3.x;
                acc.y += v0.y + v1.y + v2.y + v3.y;
                acc.z += v0.z + v1.z + v2.z + v3.z;
                acc.w += v0.w + v1.w + v2.w + v3.w;
            }
            for (; p < cnt; p++) {
                int r = __ldg(src + p);
                float4 v = __ldg(hs4 + (size_t)r * 32 + tx);
                acc.x += v.x; acc.y += v.y; acc.z += v.z; acc.w += v.w;
            }
            float dn = __ldg(g_dinv + node);
            acc.x *= dn; acc.y *= dn; acc.z *= dn; acc.w *= dn;
        }
        ((float4*)sA)[(ty * 8 + j) * 32 + tx] = acc;
    }
    __syncthreads();

    // ---- phase 1: hid = A @ Wg + bg ----
    float acc[8][4];
    {
        float4 b = __ldg((const float4*)bg + tx);
        #pragma unroll
        for (int i = 0; i < 8; i++) {
            acc[i][0] = b.x; acc[i][1] = b.y; acc[i][2] = b.z; acc[i][3] = b.w;
        }
    }
    #pragma unroll 4
    for (int k = 0; k < 128; k++) {
        float4 w = __ldg((const float4*)(Wg + k * 128) + tx);
        #pragma unroll
        for (int i = 0; i < 8; i++) {
            float a = sA[(8 * ty + i) * 128 + k];
            acc[i][0] += a * w.x;
            acc[i][1] += a * w.y;
            acc[i][2] += a * w.z;
            acc[i][3] += a * w.w;
        }
    }
    __syncthreads();

    // relu -> hidden tile
    #pragma unroll
    for (int i = 0; i < 8; i++) {
        float4 v;
        v.x = fmaxf(acc[i][0], 0.f);
        v.y = fmaxf(acc[i][1], 0.f);
        v.z = fmaxf(acc[i][2], 0.f);
        v.w = fmaxf(acc[i][3], 0.f);
        ((float4*)sA)[(8 * ty + i) * 32 + tx] = v;
    }
    __syncthreads();

    // ---- phase 2: out = hid @ Wf + bf ----
    float o[8][2];
    {
        float2 b = __ldg((const float2*)bf + tx);
        #pragma unroll
        for (int i = 0; i < 8; i++) { o[i][0] = b.x; o[i][1] = b.y; }
    }
    #pragma unroll 4
    for (int k = 0; k < 128; k++) {
        float2 w = __ldg((const float2*)(Wf + k * 64) + tx);
        #pragma unroll
        for (int i = 0; i < 8; i++) {
            float a = sA[(8 * ty + i) * 128 + k];
            o[i][0] += a * w.x;
            o[i][1] += a * w.y;
        }
    }

    #pragma unroll
    for (int i = 0; i < 8; i++) {
        int node = node0 + 8 * ty + i;
        if (node < N_NODES) {
            float2 v; v.x = o[i][0]; v.y = o[i][1];
            ((float2*)out)[(size_t)node * 32 + tx] = v;
        }
    }
}

// ---------------------------------------------------------------------------
// launch — inputs: h[f32 N*128], edge_index[2*E int32-or-int64],
//          W_gcn[f32 128*128], b_gcn[f32 128], W_fc[f32 128*64], b_fc[f32 64]
// output: f32 N*64
// ---------------------------------------------------------------------------
extern "C" void kernel_launch(void* const* d_in, const int* in_sizes, int n_in,
                              void* d_out, int out_size) {
    const float* h  = (const float*)d_in[0];
    const void*  ei = d_in[1];
    const float* Wg = (const float*)d_in[2];
    const float* bg = (const float*)d_in[3];
    const float* Wf = (const float*)d_in[4];
    const float* bf = (const float*)d_in[5];
    float* out = (float*)d_out;

    k_init<<<(N_NODES + 255) / 256, 256>>>(ei);
    k_fill<<<(N_EDGES + 255) / 256, 256>>>(ei);
    k_hs  <<<(N_NODES * 32 + 255) / 256, 256>>>(h);
    k_gather_mlp<<<(N_NODES + 63) / 64, 256>>>(Wg, bg, Wf, bf, out);
}